// round 15
// baseline (speedup 1.0000x reference)
#include <cuda_runtime.h>
#include <cuda_bf16.h>
#include <math.h>

// GRU: B=256, T=512, H=512, L=2, O=2.
// Persistent kernel; bf16 hi/lo split GEMM on mma.sync.m16n8k16 (fp32 accum).
// Fused design: activations run inside gemm-tile group epilogues (last-arriver
// pattern), h0/h1 ping-pong buffers, ONE grid barrier per step.
//   - 144 tiles of 128x64 (48 gi1 + 48 gh1 + 48 gh0), one per CTA
//   - layer-1: 16 groups of 6 tiles -> 6th arriver computes h1 block
//   - layer-0: 16 groups of 3 tiles -> 3rd arriver computes h0(t+1) block
//   - W slice pinned in smem (bf16 hi+lo); A via 4-stage cp.async, 1 sync/chunk
//   - race-free hierarchical monotonic grid barrier (round-14 validated)

#define BT 256
#define TT 512
#define HH 512
#define NG 1536
#define NCTA 148
#define NTHR 256

#define WST 520                        // W smem row stride (bf16 elems)
#define AST 40                         // A smem row stride (bf16 elems)
#define SMEM_W (64 * WST * 2)          // 66,560 B per W array (hi or lo)
#define ABUF   (128 * AST * 2)         // 10,240 B per (stage, hi/lo)
#define W_OFF  0
#define A_OFF  (2 * SMEM_W)            // 133,120
#define NSTAGE 4
#define NCHUNK 16                      // 16 chunks x 32 k
#define SMEM_BYTES (A_OFF + NSTAGE * 2 * ABUF)   // 215,040 B

// ---------------- persistent device state ----------------
__device__ __align__(16) float d_h0f[2 * BT * HH];
__device__ __align__(16) float d_h1f[2 * BT * HH];
__device__ __align__(16) __nv_bfloat16 d_h0hi[2 * BT * HH];
__device__ __align__(16) __nv_bfloat16 d_h0lo[2 * BT * HH];
__device__ __align__(16) __nv_bfloat16 d_h1hi[2 * BT * HH];
__device__ __align__(16) __nv_bfloat16 d_h1lo[2 * BT * HH];
__device__ __align__(16) float d_GA[BT * NG];
__device__ __align__(16) float d_PB0[BT * NG];
__device__ __align__(16) float d_PB1[BT * NG];
// monotonic counters (zeroed each launch by gru_init)
__device__ unsigned d_grpCount[16 * 32];     // barrier groups
__device__ unsigned d_rootCount;
__device__ volatile unsigned d_barGen;
__device__ unsigned d_g1cnt[16 * 32];        // layer-1 tile groups (6 arrivals/step)
__device__ unsigned d_g0cnt[16 * 32];        // layer-0 tile groups (3 arrivals/step)

__global__ void gru_init()
{
    int i  = blockIdx.x * blockDim.x + threadIdx.x;
    int st = gridDim.x * blockDim.x;
    for (int e = i; e < 2 * BT * HH; e += st) { d_h0f[e] = 0.f; d_h1f[e] = 0.f; }
    unsigned* z0 = (unsigned*)d_h0hi; unsigned* z1 = (unsigned*)d_h0lo;
    unsigned* z2 = (unsigned*)d_h1hi; unsigned* z3 = (unsigned*)d_h1lo;
    for (int e = i; e < BT * HH; e += st) { z0[e] = 0u; z1[e] = 0u; z2[e] = 0u; z3[e] = 0u; }
    for (int e = i; e < BT * NG; e += st) d_GA[e] = 0.f;
    if (i < 16 * 32) { d_grpCount[i] = 0u; d_g1cnt[i] = 0u; d_g0cnt[i] = 0u; }
    if (i == 0) { d_rootCount = 0u; d_barGen = 0u; }
}

// ---------------- race-free hierarchical grid barrier (monotonic) ----------------
__device__ __forceinline__ void gridBarrier()
{
    __syncthreads();
    if (threadIdx.x == 0) {
        __threadfence();
        unsigned gen = d_barGen;
        unsigned grp = blockIdx.x & 15u;
        unsigned gsz = (grp < (NCTA & 15u)) ? (NCTA / 16 + 1) : (NCTA / 16);
        unsigned arrived = atomicAdd(&d_grpCount[grp * 32], 1u) + 1u;
        if (arrived == (gen + 1u) * gsz) {
            unsigned rootArr = atomicAdd(&d_rootCount, 1u) + 1u;
            if (rootArr == (gen + 1u) * 16u) {
                __threadfence();
                d_barGen = gen + 1u;
            }
        }
        while (d_barGen == gen) __nanosleep(32);
        __threadfence();
    }
    __syncthreads();
}

// ---------------- cp.async + misc PTX ----------------
__device__ __forceinline__ unsigned s2u(const void* p)
{
    unsigned a;
    asm("{ .reg .u64 t; cvta.to.shared.u64 t, %1; cvt.u32.u64 %0, t; }" : "=r"(a) : "l"(p));
    return a;
}
#define CPA16(d, s)  asm volatile("cp.async.cg.shared.global [%0], [%1], 16;" :: "r"(d), "l"(s) : "memory")
#define CP_COMMIT()  asm volatile("cp.async.commit_group;" ::: "memory")
#define CP_WAIT2()   asm volatile("cp.async.wait_group 2;" ::: "memory")
#define CP_WAIT0()   asm volatile("cp.async.wait_group 0;" ::: "memory")

#define MMA16816(C, A, b0, b1)                                                  \
    asm volatile("mma.sync.aligned.m16n8k16.row.col.f32.bf16.bf16.f32 "         \
                 "{%0,%1,%2,%3},{%4,%5,%6,%7},{%8,%9},{%0,%1,%2,%3};"           \
                 : "+f"((C)[0]), "+f"((C)[1]), "+f"((C)[2]), "+f"((C)[3])       \
                 : "r"((A)[0]), "r"((A)[1]), "r"((A)[2]), "r"((A)[3]),          \
                   "r"(b0), "r"(b1))

// ---------------- bf16 split helpers ----------------
__device__ __forceinline__ unsigned pack_bf2(float a, float b)
{
    __nv_bfloat162 t = __floats2bfloat162_rn(a, b);
    return *reinterpret_cast<unsigned*>(&t);
}
__device__ __forceinline__ float bflo(float v)
{
    return v - __bfloat162float(__float2bfloat16_rn(v));
}

// ---------------- one-time weight slice -> smem (bf16 hi/lo) ----------------
__device__ void preloadW(const float* __restrict__ Wsl, char* smem)
{
    __nv_bfloat16* Whi = (__nv_bfloat16*)(smem + W_OFF);
    __nv_bfloat16* Wlo = (__nv_bfloat16*)(smem + W_OFF + SMEM_W);
    for (int idx = threadIdx.x; idx < 64 * (HH / 4); idx += NTHR) {
        int n  = idx >> 7;
        int k4 = (idx & 127) << 2;
        float4 w = *(const float4*)(Wsl + n * HH + k4);
        uint2 hv, lv;
        hv.x = pack_bf2(w.x, w.y);             hv.y = pack_bf2(w.z, w.w);
        lv.x = pack_bf2(bflo(w.x), bflo(w.y)); lv.y = pack_bf2(bflo(w.z), bflo(w.w));
        *(uint2*)(Whi + n * WST + k4) = hv;
        *(uint2*)(Wlo + n * WST + k4) = lv;
    }
}

// ---------------- cp.async stage of one 32-k A chunk (hi+lo) ----------------
__device__ __forceinline__ void issueChunk(const __nv_bfloat16* __restrict__ Ahi,
                                           const __nv_bfloat16* __restrict__ Alo,
                                           unsigned smem_u, int stage, int m0, int c)
{
    int t = threadIdx.x;
    int row = t >> 1, half = t & 1;
    const char* gh = (const char*)(Ahi + (m0 + row) * HH + c * 32 + half * 16);
    const char* gl = (const char*)(Alo + (m0 + row) * HH + c * 32 + half * 16);
    unsigned bh = smem_u + A_OFF + (stage * 2 + 0) * ABUF + row * (AST * 2) + half * 32;
    unsigned bl = smem_u + A_OFF + (stage * 2 + 1) * ABUF + row * (AST * 2) + half * 32;
    CPA16(bh, gh);      CPA16(bh + 16, gh + 16);
    CPA16(bl, gl);      CPA16(bl + 16, gl + 16);
}

// ---------------- per-step 128x64xK512 tile gemm (split bf16, fp32 accum) ----------------
__device__ void tileStep(const __nv_bfloat16* __restrict__ Agh,
                         const __nv_bfloat16* __restrict__ Agl,
                         float* __restrict__ Cg, int m0, int n0,
                         char* smem, unsigned smem_u)
{
    const __nv_bfloat16* Whi = (const __nv_bfloat16*)(smem + W_OFF);
    const __nv_bfloat16* Wlo = (const __nv_bfloat16*)(smem + W_OFF + SMEM_W);

    const int tid  = threadIdx.x;
    const int wid  = tid >> 5;
    const int lane = tid & 31;
    const int g    = lane >> 2;
    const int t4   = lane & 3;
    const int wm   = wid & 1;
    const int wn   = wid >> 1;

    int aoff[4];
#pragma unroll
    for (int ma = 0; ma < 4; ++ma)
        aoff[ma] = (wm * 64 + ma * 16 + g) * AST + 2 * t4;
    int boff[2];
#pragma unroll
    for (int na = 0; na < 2; ++na)
        boff[na] = (wn * 16 + na * 8 + g) * WST + 2 * t4;

    float acc[4][2][4];
#pragma unroll
    for (int ma = 0; ma < 4; ++ma)
#pragma unroll
        for (int na = 0; na < 2; ++na)
#pragma unroll
            for (int q = 0; q < 4; ++q) acc[ma][na][q] = 0.f;

    // prologue: fill 3 of 4 stages
#pragma unroll
    for (int s = 0; s < 3; ++s) {
        issueChunk(Agh, Agl, smem_u, s, m0, s);
        CP_COMMIT();
    }

#pragma unroll 1
    for (int c = 0; c < NCHUNK; ++c) {
        // committed before this iter: 3 + c groups; chunk c done <=> <=2 pending
        CP_WAIT2();
        __syncthreads();           // (a) chunk c visible to all; (b) all warps done with chunk c-1
        if (c + 3 < NCHUNK)        // issue into stage freed by chunk c-1
            issueChunk(Agh, Agl, smem_u, (c + 3) & 3, m0, c + 3);
        CP_COMMIT();               // always commit (possibly empty) to keep accounting

        int stg = c & 3;
        const __nv_bfloat16* Ah = (const __nv_bfloat16*)(smem + A_OFF + (stg * 2 + 0) * ABUF);
        const __nv_bfloat16* Al = (const __nv_bfloat16*)(smem + A_OFF + (stg * 2 + 1) * ABUF);
#pragma unroll
        for (int ks = 0; ks < 32; ks += 16) {
            unsigned ah[4][4], al[4][4];
#pragma unroll
            for (int ma = 0; ma < 4; ++ma) {
                int o = aoff[ma] + ks;
                ah[ma][0] = *(const unsigned*)(Ah + o);
                ah[ma][1] = *(const unsigned*)(Ah + o + 8 * AST);
                ah[ma][2] = *(const unsigned*)(Ah + o + 8);
                ah[ma][3] = *(const unsigned*)(Ah + o + 8 * AST + 8);
                al[ma][0] = *(const unsigned*)(Al + o);
                al[ma][1] = *(const unsigned*)(Al + o + 8 * AST);
                al[ma][2] = *(const unsigned*)(Al + o + 8);
                al[ma][3] = *(const unsigned*)(Al + o + 8 * AST + 8);
            }
#pragma unroll
            for (int na = 0; na < 2; ++na) {
                int ob = boff[na] + c * 32 + ks;
                unsigned bh0 = *(const unsigned*)(Whi + ob);
                unsigned bh1 = *(const unsigned*)(Whi + ob + 8);
                unsigned bl0 = *(const unsigned*)(Wlo + ob);
                unsigned bl1 = *(const unsigned*)(Wlo + ob + 8);
#pragma unroll
                for (int ma = 0; ma < 4; ++ma) {
                    MMA16816(acc[ma][na], ah[ma], bh0, bh1);
                    MMA16816(acc[ma][na], ah[ma], bl0, bl1);
                    MMA16816(acc[ma][na], al[ma], bh0, bh1);
                }
            }
        }
    }
    CP_WAIT0();

    // epilogue: store C (fenced before group-arrive by caller)
#pragma unroll
    for (int ma = 0; ma < 4; ++ma) {
        int row = m0 + wm * 64 + ma * 16 + g;
#pragma unroll
        for (int na = 0; na < 2; ++na) {
            int col = n0 + wn * 16 + na * 8 + 2 * t4;
            float2 v0; v0.x = acc[ma][na][0]; v0.y = acc[ma][na][1];
            float2 v1; v1.x = acc[ma][na][2]; v1.y = acc[ma][na][3];
            *(float2*)(Cg + row * NG + col)       = v0;
            *(float2*)(Cg + (row + 8) * NG + col) = v1;
        }
    }
}

// ---------------- fused activations (group winners) ----------------
__device__ __forceinline__ float sigmoidf_(float v) { return 1.f / (1.f + expf(-v)); }

// compute h1 for block [m0:m0+128) x [n0w:n0w+64) from PB0/PB1 (this step's tiles)
__device__ void actH1win(int m0, int n0w, int par,
                         const float* __restrict__ bi1, const float* __restrict__ bh)
{
    const int po = par * BT * HH, pn = (par ^ 1) * BT * HH;
    for (int it = threadIdx.x; it < 2048; it += NTHR) {
        int row = it >> 4, c4 = it & 15;
        int b = m0 + row;
        int n = n0w + (c4 << 2);
        const float* P0 = d_PB0 + b * NG + n;
        const float* P1 = d_PB1 + b * NG + n;
        float4 i0 = __ldcg((const float4*)(P0));
        float4 i1 = __ldcg((const float4*)(P0 + 512));
        float4 i2 = __ldcg((const float4*)(P0 + 1024));
        float4 g0 = __ldcg((const float4*)(P1));
        float4 g1 = __ldcg((const float4*)(P1 + 512));
        float4 g2 = __ldcg((const float4*)(P1 + 1024));
        float4 c0 = *(const float4*)(bi1 + n);
        float4 c1 = *(const float4*)(bi1 + 512 + n);
        float4 c2 = *(const float4*)(bi1 + 1024 + n);
        float4 d0 = *(const float4*)(bh + NG + n);
        float4 d1 = *(const float4*)(bh + NG + 512 + n);
        float4 d2 = *(const float4*)(bh + NG + 1024 + n);
        float4 ho = __ldcg((const float4*)(d_h1f + po + b * HH + n));
        float4 res;
        const float *pi0 = (const float*)&i0, *pi1 = (const float*)&i1, *pi2 = (const float*)&i2;
        const float *pg0 = (const float*)&g0, *pg1 = (const float*)&g1, *pg2 = (const float*)&g2;
        const float *pc0 = (const float*)&c0, *pc1 = (const float*)&c1, *pc2 = (const float*)&c2;
        const float *pd0 = (const float*)&d0, *pd1 = (const float*)&d1, *pd2 = (const float*)&d2;
        const float *pho = (const float*)&ho;
        float* pr = (float*)&res;
#pragma unroll
        for (int l = 0; l < 4; ++l) {
            float r  = sigmoidf_(pi0[l] + pc0[l] + pg0[l] + pd0[l]);
            float z  = sigmoidf_(pi1[l] + pc1[l] + pg1[l] + pd1[l]);
            float nn = tanhf(pi2[l] + pc2[l] + r * (pg2[l] + pd2[l]));
            pr[l] = (1.f - z) * nn + z * pho[l];
        }
        *(float4*)(d_h1f + pn + b * HH + n) = res;
        uint2 hv, lv;
        hv.x = pack_bf2(res.x, res.y);             hv.y = pack_bf2(res.z, res.w);
        lv.x = pack_bf2(bflo(res.x), bflo(res.y)); lv.y = pack_bf2(bflo(res.z), bflo(res.w));
        *(uint2*)(d_h1hi + pn + b * HH + n) = hv;
        *(uint2*)(d_h1lo + pn + b * HH + n) = lv;
    }
}

// compute h0(t+1) for block from GA (this step's gh0 tiles) + x[:, t+1]
__device__ void actH0win(int m0, int n0w, int par, int t,
                         const float* __restrict__ x, const float* __restrict__ Wi0,
                         const float* __restrict__ bi0, const float* __restrict__ bh)
{
    const int po = par * BT * HH, pn = (par ^ 1) * BT * HH;
    for (int it = threadIdx.x; it < 2048; it += NTHR) {
        int row = it >> 4, c4 = it & 15;
        int b = m0 + row;
        int n = n0w + (c4 << 2);
        float xv = x[b * TT + t + 1];
        const float* G = d_GA + b * NG + n;
        float4 g0 = __ldcg((const float4*)(G));
        float4 g1 = __ldcg((const float4*)(G + 512));
        float4 g2 = __ldcg((const float4*)(G + 1024));
        float4 w0 = *(const float4*)(Wi0 + n);
        float4 w1 = *(const float4*)(Wi0 + 512 + n);
        float4 w2 = *(const float4*)(Wi0 + 1024 + n);
        float4 c0 = *(const float4*)(bi0 + n);
        float4 c1 = *(const float4*)(bi0 + 512 + n);
        float4 c2 = *(const float4*)(bi0 + 1024 + n);
        float4 d0 = *(const float4*)(bh + n);
        float4 d1 = *(const float4*)(bh + 512 + n);
        float4 d2 = *(const float4*)(bh + 1024 + n);
        float4 ho = __ldcg((const float4*)(d_h0f + po + b * HH + n));
        float4 res;
        const float *pg0 = (const float*)&g0, *pg1 = (const float*)&g1, *pg2 = (const float*)&g2;
        const float *pw0 = (const float*)&w0, *pw1 = (const float*)&w1, *pw2 = (const float*)&w2;
        const float *pc0 = (const float*)&c0, *pc1 = (const float*)&c1, *pc2 = (const float*)&c2;
        const float *pd0 = (const float*)&d0, *pd1 = (const float*)&d1, *pd2 = (const float*)&d2;
        const float *pho = (const float*)&ho;
        float* pr = (float*)&res;
#pragma unroll
        for (int l = 0; l < 4; ++l) {
            float r  = sigmoidf_(pg0[l] + pd0[l] + xv * pw0[l] + pc0[l]);
            float z  = sigmoidf_(pg1[l] + pd1[l] + xv * pw1[l] + pc1[l]);
            float nn = tanhf(xv * pw2[l] + pc2[l] + r * (pg2[l] + pd2[l]));
            pr[l] = (1.f - z) * nn + z * pho[l];
        }
        *(float4*)(d_h0f + pn + b * HH + n) = res;
        uint2 hv, lv;
        hv.x = pack_bf2(res.x, res.y);             hv.y = pack_bf2(res.z, res.w);
        lv.x = pack_bf2(bflo(res.x), bflo(res.y)); lv.y = pack_bf2(bflo(res.z), bflo(res.w));
        *(uint2*)(d_h0hi + pn + b * HH + n) = hv;
        *(uint2*)(d_h0lo + pn + b * HH + n) = lv;
    }
}

// ---------------- final FC (h1 final lives in buffer 0: (511&1)^1 = 0) ----------------
__device__ void fcOut(const float* __restrict__ fcw, const float* __restrict__ fcb,
                      float* __restrict__ out)
{
    __shared__ float red[2][8];
    if (blockIdx.x >= 128) return;
    for (int s = 0; s < 2; ++s) {
        int b = blockIdx.x * 2 + s;
        float p0 = 0.f, p1 = 0.f;
        for (int k = threadIdx.x; k < HH; k += NTHR) {
            float h = d_h1f[b * HH + k];
            p0 += h * fcw[k];
            p1 += h * fcw[HH + k];
        }
#pragma unroll
        for (int o = 16; o; o >>= 1) {
            p0 += __shfl_down_sync(0xffffffffu, p0, o);
            p1 += __shfl_down_sync(0xffffffffu, p1, o);
        }
        int w = threadIdx.x >> 5;
        if ((threadIdx.x & 31) == 0) { red[0][w] = p0; red[1][w] = p1; }
        __syncthreads();
        if (threadIdx.x == 0) {
            float a0 = 0.f, a1 = 0.f;
#pragma unroll
            for (int ww = 0; ww < 8; ++ww) { a0 += red[0][ww]; a1 += red[1][ww]; }
            out[b * 2 + 0] = a0 + fcb[0];
            out[b * 2 + 1] = a1 + fcb[1];
        }
        __syncthreads();
    }
}

// ---------------- persistent kernel ----------------
__global__ void __launch_bounds__(NTHR, 1)
gru_persistent(const float* __restrict__ x,   const float* __restrict__ Wi0,
               const float* __restrict__ bi0, const float* __restrict__ Wi1,
               const float* __restrict__ bi1, const float* __restrict__ Wh,
               const float* __restrict__ bh,  const float* __restrict__ fcw,
               const float* __restrict__ fcb, float* __restrict__ out)
{
    extern __shared__ char smem[];
    __shared__ unsigned sWin;
    const unsigned smem_u = s2u(smem);
    const int tid = threadIdx.x;

    // fixed tile assignment: u = gsel*48 + m*24 + gate*8 + nw
    const int u = blockIdx.x;
    const bool active = (u < 144);
    const int gsel = u / 48;           // 0: gi1, 1: gh1, 2: gh0(next step)
    const int tb   = u % 48;
    const int m    = tb / 24;
    const int tc   = tb % 24;          // gate*8 + nw
    const int nw   = tc % 8;
    const int m0   = m * 128;
    const int n0   = tc * 64;          // column in NG space
    const int n0w  = nw * 64;          // column within one gate (512)
    const int gid  = m * 8 + nw;       // act-group id (0..15)

    float* Cg = (gsel == 0) ? d_PB0 : ((gsel == 1) ? d_PB1 : d_GA);

    if (active) {
        const float* Wsl = (gsel == 0) ? (Wi1 + n0 * HH)
                         : (gsel == 1) ? (Wh + NG * HH + n0 * HH)
                                       : (Wh + n0 * HH);
        preloadW(Wsl, smem);
    }
    __syncthreads();

    // prologue: h0(0) into buffer 0 (h_old = 0, GA = 0)
    {
        int gtid = blockIdx.x * NTHR + tid;
        int st   = gridDim.x * NTHR;
        for (int idx = gtid; idx < (BT * HH) / 4; idx += st) {
            int b = idx >> 7;
            int n = (idx & 127) << 2;
            float xv = x[b * TT];
            float4 w0 = *(const float4*)(Wi0 + n);
            float4 w1 = *(const float4*)(Wi0 + 512 + n);
            float4 w2 = *(const float4*)(Wi0 + 1024 + n);
            float4 c0 = *(const float4*)(bi0 + n);
            float4 c1 = *(const float4*)(bi0 + 512 + n);
            float4 c2 = *(const float4*)(bi0 + 1024 + n);
            float4 d0 = *(const float4*)(bh + n);
            float4 d1 = *(const float4*)(bh + 512 + n);
            float4 d2 = *(const float4*)(bh + 1024 + n);
            float4 res;
            const float *pw0 = (const float*)&w0, *pw1 = (const float*)&w1, *pw2 = (const float*)&w2;
            const float *pc0 = (const float*)&c0, *pc1 = (const float*)&c1, *pc2 = (const float*)&c2;
            const float *pd0 = (const float*)&d0, *pd1 = (const float*)&d1, *pd2 = (const float*)&d2;
            float* pr = (float*)&res;
#pragma unroll
            for (int l = 0; l < 4; ++l) {
                float r  = sigmoidf_(xv * pw0[l] + pc0[l] + pd0[l]);
                float z  = sigmoidf_(xv * pw1[l] + pc1[l] + pd1[l]);
                float nn = tanhf(xv * pw2[l] + pc2[l] + r * pd2[l]);
                pr[l] = (1.f - z) * nn;
            }
            *(float4*)(d_h0f + b * HH + n) = res;
            uint2 hv, lv;
            hv.x = pack_bf2(res.x, res.y);             hv.y = pack_bf2(res.z, res.w);
            lv.x = pack_bf2(bflo(res.x), bflo(res.y)); lv.y = pack_bf2(bflo(res.z), bflo(res.w));
            *(uint2*)(d_h0hi + b * HH + n) = hv;
            *(uint2*)(d_h0lo + b * HH + n) = lv;
        }
    }
    gridBarrier();

    for (int t = 0; t < TT; ++t) {
        int par = t & 1;
        bool run = active && (t < TT - 1 || gsel < 2);   // gh0 skips last step
        if (run) {
            const __nv_bfloat16* Agh = ((gsel == 1) ? d_h1hi : d_h0hi) + par * BT * HH;
            const __nv_bfloat16* Agl = ((gsel == 1) ? d_h1lo : d_h0lo) + par * BT * HH;
            tileStep(Agh, Agl, Cg, m0, n0, smem, smem_u);
            __threadfence();           // release C-tile stores
            if (tid == 0) {
                unsigned need = (gsel < 2) ? 6u : 3u;
                unsigned* cnt = (gsel < 2) ? &d_g1cnt[gid * 32] : &d_g0cnt[gid * 32];
                unsigned a = atomicAdd(cnt, 1u) + 1u;
                sWin = (a == need * (unsigned)(t + 1)) ? 1u : 0u;
            }
            __syncthreads();
            if (sWin) {
                __threadfence();       // acquire peers' C-tile stores
                if (gsel < 2) actH1win(m0, n0w, par, bi1, bh);
                else          actH0win(m0, n0w, par, t, x, Wi0, bi0, bh);
            }
        }
        gridBarrier();
    }

    fcOut(fcw, fcb, out);
}

// ---------------- launch ----------------
extern "C" void kernel_launch(void* const* d_in, const int* in_sizes, int n_in,
                              void* d_out, int out_size)
{
    (void)in_sizes; (void)n_in; (void)out_size;
    const float* x   = (const float*)d_in[0];
    const float* Wi0 = (const float*)d_in[1];
    const float* bi0 = (const float*)d_in[2];
    const float* Wi1 = (const float*)d_in[3];
    const float* bi1 = (const float*)d_in[4];
    const float* Wh  = (const float*)d_in[5];
    const float* bh  = (const float*)d_in[6];
    const float* fcw = (const float*)d_in[7];
    const float* fcb = (const float*)d_in[8];
    float* out = (float*)d_out;

    cudaFuncSetAttribute(gru_persistent,
                         cudaFuncAttributeMaxDynamicSharedMemorySize, SMEM_BYTES);

    gru_init<<<64, 256>>>();
    gru_persistent<<<NCTA, NTHR, SMEM_BYTES>>>(x, Wi0, bi0, Wi1, bi1, Wh, bh,
                                               fcw, fcb, out);
}

// round 16
// speedup vs baseline: 1.2323x; 1.2323x over previous
#include <cuda_runtime.h>
#include <cuda_bf16.h>
#include <math.h>

// GRU: B=256, T=512, H=512, L=2, O=2.
// Persistent kernel; bf16 hi/lo split GEMM on mma.sync.m16n8k16 (fp32 accum).
// Round-11 structure with SPLIT-K=2: each 128x64 tile computed by two CTAs
// (K halves of 256), partials in duplicated C buffers summed by the acts.
// 288 CTAs, 2/SM -> 4 warps/SMSP to hide MMA/LDS dependency stalls.
// Race-free monotonic hierarchical grid barrier (round-14 validated).

#define BT 256
#define TT 512
#define HH 512
#define NG 1536
#define NCTA 288
#define NTHR 256

#define KSL 256                        // K per split
#define WST 264                        // W smem row stride (bf16 elems, 256+8)
#define AST 40                         // A smem row stride (bf16 elems, 32+8)
#define SMEM_W (64 * WST * 2)          // 33,792 B per W array (hi or lo)
#define ABUF   (128 * AST * 2)         // 10,240 B per (stage, hi/lo)
#define W_OFF  0
#define A_OFF  (2 * SMEM_W)            // 67,584
#define NSTAGE 2
#define NCHUNK 8                       // 8 chunks x 32 k = 256
#define SMEM_BYTES (A_OFF + NSTAGE * 2 * ABUF)   // 108,544 B  (x2 CTAs = 217KB/SM)

// ---------------- persistent device state ----------------
__device__ __align__(16) float d_h0[BT * HH];
__device__ __align__(16) float d_h1[BT * HH];
__device__ __align__(16) __nv_bfloat16 d_h0hi[BT * HH];
__device__ __align__(16) __nv_bfloat16 d_h0lo[BT * HH];
__device__ __align__(16) __nv_bfloat16 d_h1hi[BT * HH];
__device__ __align__(16) __nv_bfloat16 d_h1lo[BT * HH];
__device__ __align__(16) float d_GA [2][BT * NG];   // split-K partials
__device__ __align__(16) float d_PB0[2][BT * NG];
__device__ __align__(16) float d_PB1[2][BT * NG];
// race-free barrier: monotonic counters, zeroed each launch by gru_init
__device__ unsigned d_grpCount[16 * 32];
__device__ unsigned d_rootCount;
__device__ volatile unsigned d_barGen;

__global__ void gru_init()
{
    int i  = blockIdx.x * blockDim.x + threadIdx.x;
    int st = gridDim.x * blockDim.x;
    for (int e = i; e < BT * HH; e += st) { d_h0[e] = 0.f; d_h1[e] = 0.f; }
    unsigned* z0 = (unsigned*)d_h0hi; unsigned* z1 = (unsigned*)d_h0lo;
    unsigned* z2 = (unsigned*)d_h1hi; unsigned* z3 = (unsigned*)d_h1lo;
    for (int e = i; e < (BT * HH) / 2; e += st) { z0[e] = 0u; z1[e] = 0u; z2[e] = 0u; z3[e] = 0u; }
    for (int e = i; e < 2 * BT * NG; e += st) ((float*)d_GA)[e] = 0.f;
    if (i < 16 * 32) d_grpCount[i] = 0u;
    if (i == 0) { d_rootCount = 0u; d_barGen = 0u; }
}

// ---------------- race-free hierarchical grid barrier (monotonic) ----------------
__device__ __forceinline__ void gridBarrier()
{
    __syncthreads();
    if (threadIdx.x == 0) {
        __threadfence();
        unsigned gen = d_barGen;
        unsigned grp = blockIdx.x & 15u;
        unsigned gsz = NCTA / 16;                      // 288/16 = 18 exactly
        unsigned arrived = atomicAdd(&d_grpCount[grp * 32], 1u) + 1u;
        if (arrived == (gen + 1u) * gsz) {
            unsigned rootArr = atomicAdd(&d_rootCount, 1u) + 1u;
            if (rootArr == (gen + 1u) * 16u) {
                __threadfence();
                d_barGen = gen + 1u;
            }
        }
        while (d_barGen == gen) __nanosleep(32);
        __threadfence();
    }
    __syncthreads();
}

// ---------------- cp.async + misc PTX ----------------
__device__ __forceinline__ unsigned s2u(const void* p)
{
    unsigned a;
    asm("{ .reg .u64 t; cvta.to.shared.u64 t, %1; cvt.u32.u64 %0, t; }" : "=r"(a) : "l"(p));
    return a;
}
#define CPA16(d, s)  asm volatile("cp.async.cg.shared.global [%0], [%1], 16;" :: "r"(d), "l"(s) : "memory")
#define CP_COMMIT()  asm volatile("cp.async.commit_group;" ::: "memory")
#define CP_WAIT1()   asm volatile("cp.async.wait_group 1;" ::: "memory")
#define CP_WAIT0()   asm volatile("cp.async.wait_group 0;" ::: "memory")

#define MMA16816(C, A, b0, b1)                                                  \
    asm volatile("mma.sync.aligned.m16n8k16.row.col.f32.bf16.bf16.f32 "         \
                 "{%0,%1,%2,%3},{%4,%5,%6,%7},{%8,%9},{%0,%1,%2,%3};"           \
                 : "+f"((C)[0]), "+f"((C)[1]), "+f"((C)[2]), "+f"((C)[3])       \
                 : "r"((A)[0]), "r"((A)[1]), "r"((A)[2]), "r"((A)[3]),          \
                   "r"(b0), "r"(b1))

// ---------------- bf16 split helpers ----------------
__device__ __forceinline__ unsigned pack_bf2(float a, float b)
{
    __nv_bfloat162 t = __floats2bfloat162_rn(a, b);
    return *reinterpret_cast<unsigned*>(&t);
}
__device__ __forceinline__ float bflo(float v)
{
    return v - __bfloat162float(__float2bfloat16_rn(v));
}

// ---------------- one-time weight slice (64 x 256) -> smem (bf16 hi/lo) ----------------
__device__ void preloadW(const float* __restrict__ Wsl, char* smem)
{
    __nv_bfloat16* Whi = (__nv_bfloat16*)(smem + W_OFF);
    __nv_bfloat16* Wlo = (__nv_bfloat16*)(smem + W_OFF + SMEM_W);
    for (int idx = threadIdx.x; idx < 64 * (KSL / 4); idx += NTHR) {
        int n  = idx >> 6;             // 0..63
        int k4 = (idx & 63) << 2;      // 0..252
        float4 w = *(const float4*)(Wsl + n * HH + k4);
        uint2 hv, lv;
        hv.x = pack_bf2(w.x, w.y);             hv.y = pack_bf2(w.z, w.w);
        lv.x = pack_bf2(bflo(w.x), bflo(w.y)); lv.y = pack_bf2(bflo(w.z), bflo(w.w));
        *(uint2*)(Whi + n * WST + k4) = hv;
        *(uint2*)(Wlo + n * WST + k4) = lv;
    }
}

// ---------------- cp.async stage of one 32-k A chunk (hi+lo) ----------------
__device__ __forceinline__ void issueChunk(const __nv_bfloat16* __restrict__ Ahi,
                                           const __nv_bfloat16* __restrict__ Alo,
                                           unsigned smem_u, int stage, int m0,
                                           int kbase, int c)
{
    int t = threadIdx.x;
    int row = t >> 1, half = t & 1;
    const char* gh = (const char*)(Ahi + (m0 + row) * HH + kbase + c * 32 + half * 16);
    const char* gl = (const char*)(Alo + (m0 + row) * HH + kbase + c * 32 + half * 16);
    unsigned bh = smem_u + A_OFF + (stage * 2 + 0) * ABUF + row * (AST * 2) + half * 32;
    unsigned bl = smem_u + A_OFF + (stage * 2 + 1) * ABUF + row * (AST * 2) + half * 32;
    CPA16(bh, gh);      CPA16(bh + 16, gh + 16);
    CPA16(bl, gl);      CPA16(bl + 16, gl + 16);
}

// ---------------- per-step 128x64xK256 half-tile gemm (split bf16, fp32 accum) ----------------
__device__ void tileStep(const __nv_bfloat16* __restrict__ Agh,
                         const __nv_bfloat16* __restrict__ Agl,
                         float* __restrict__ Cg, int m0, int n0, int kbase,
                         char* smem, unsigned smem_u)
{
    const __nv_bfloat16* Whi = (const __nv_bfloat16*)(smem + W_OFF);
    const __nv_bfloat16* Wlo = (const __nv_bfloat16*)(smem + W_OFF + SMEM_W);

    const int tid  = threadIdx.x;
    const int wid  = tid >> 5;
    const int lane = tid & 31;
    const int g    = lane >> 2;
    const int t4   = lane & 3;
    const int wm   = wid & 1;
    const int wn   = wid >> 1;

    int aoff[4];
#pragma unroll
    for (int ma = 0; ma < 4; ++ma)
        aoff[ma] = (wm * 64 + ma * 16 + g) * AST + 2 * t4;
    int boff[2];
#pragma unroll
    for (int na = 0; na < 2; ++na)
        boff[na] = (wn * 16 + na * 8 + g) * WST + 2 * t4;

    float acc[4][2][4];
#pragma unroll
    for (int ma = 0; ma < 4; ++ma)
#pragma unroll
        for (int na = 0; na < 2; ++na)
#pragma unroll
            for (int q = 0; q < 4; ++q) acc[ma][na][q] = 0.f;

    // prologue: fill both stages (prior step's reads fenced by grid barrier)
#pragma unroll
    for (int s = 0; s < NSTAGE; ++s) {
        issueChunk(Agh, Agl, smem_u, s, m0, kbase, s);
        CP_COMMIT();
    }

#pragma unroll 1
    for (int c = 0; c < NCHUNK; ++c) {
        int stg = c & 1;
        CP_WAIT1();                // chunk c's group complete
        __syncthreads();

        const __nv_bfloat16* Ah = (const __nv_bfloat16*)(smem + A_OFF + (stg * 2 + 0) * ABUF);
        const __nv_bfloat16* Al = (const __nv_bfloat16*)(smem + A_OFF + (stg * 2 + 1) * ABUF);
#pragma unroll
        for (int ks = 0; ks < 32; ks += 16) {
            unsigned ah[4][4], al[4][4];
#pragma unroll
            for (int ma = 0; ma < 4; ++ma) {
                int o = aoff[ma] + ks;
                ah[ma][0] = *(const unsigned*)(Ah + o);
                ah[ma][1] = *(const unsigned*)(Ah + o + 8 * AST);
                ah[ma][2] = *(const unsigned*)(Ah + o + 8);
                ah[ma][3] = *(const unsigned*)(Ah + o + 8 * AST + 8);
                al[ma][0] = *(const unsigned*)(Al + o);
                al[ma][1] = *(const unsigned*)(Al + o + 8 * AST);
                al[ma][2] = *(const unsigned*)(Al + o + 8);
                al[ma][3] = *(const unsigned*)(Al + o + 8 * AST + 8);
            }
#pragma unroll
            for (int na = 0; na < 2; ++na) {
                int ob = boff[na] + c * 32 + ks;
                unsigned bh0 = *(const unsigned*)(Whi + ob);
                unsigned bh1 = *(const unsigned*)(Whi + ob + 8);
                unsigned bl0 = *(const unsigned*)(Wlo + ob);
                unsigned bl1 = *(const unsigned*)(Wlo + ob + 8);
#pragma unroll
                for (int ma = 0; ma < 4; ++ma) {
                    MMA16816(acc[ma][na], ah[ma], bh0, bh1);   // hi*hi
                    MMA16816(acc[ma][na], ah[ma], bl0, bl1);   // hi*lo
                    MMA16816(acc[ma][na], al[ma], bh0, bh1);   // lo*hi
                }
            }
        }

        __syncthreads();           // all warps done reading stage stg (WAR)
        if (c + NSTAGE < NCHUNK)
            issueChunk(Agh, Agl, smem_u, stg, m0, kbase, c + NSTAGE);
        CP_COMMIT();               // commit (possibly empty) to keep group count
    }
    CP_WAIT0();

    // epilogue: per-lane fragment layout of C (m16n8)
#pragma unroll
    for (int ma = 0; ma < 4; ++ma) {
        int row = m0 + wm * 64 + ma * 16 + g;
#pragma unroll
        for (int na = 0; na < 2; ++na) {
            int col = n0 + wn * 16 + na * 8 + 2 * t4;
            float2 v0; v0.x = acc[ma][na][0]; v0.y = acc[ma][na][1];
            float2 v1; v1.x = acc[ma][na][2]; v1.y = acc[ma][na][3];
            *(float2*)(Cg + row * NG + col)       = v0;
            *(float2*)(Cg + (row + 8) * NG + col) = v1;
        }
    }
}

// ---------------- activations (exact; sum split-K partials; emit bf16 hi/lo) ----------------
__device__ __forceinline__ float sigmoidf_(float v) { return 1.f / (1.f + expf(-v)); }
__device__ __forceinline__ float4 add4(float4 a, float4 b)
{
    float4 r; r.x = a.x + b.x; r.y = a.y + b.y; r.z = a.z + b.z; r.w = a.w + b.w;
    return r;
}

__device__ void actA(const float* __restrict__ x, const float* __restrict__ Wi0,
                     const float* __restrict__ bi0, const float* __restrict__ bh, int t)
{
    int gtid = blockIdx.x * blockDim.x + threadIdx.x;
    int st   = gridDim.x * blockDim.x;
    for (int idx = gtid; idx < (BT * HH) / 4; idx += st) {
        int b = idx >> 7;
        int n = (idx & 127) << 2;
        float xv = x[b * TT + t];
        const float* Ga = d_GA[0] + b * NG + n;
        const float* Gb = d_GA[1] + b * NG + n;
        float4 g0 = add4(*(const float4*)(Ga),            *(const float4*)(Gb));
        float4 g1 = add4(*(const float4*)(Ga + HH),       *(const float4*)(Gb + HH));
        float4 g2 = add4(*(const float4*)(Ga + 2 * HH),   *(const float4*)(Gb + 2 * HH));
        float4 w0 = *(const float4*)(Wi0 + n);
        float4 w1 = *(const float4*)(Wi0 + HH + n);
        float4 w2 = *(const float4*)(Wi0 + 2 * HH + n);
        float4 c0 = *(const float4*)(bi0 + n);
        float4 c1 = *(const float4*)(bi0 + HH + n);
        float4 c2 = *(const float4*)(bi0 + 2 * HH + n);
        float4 d0 = *(const float4*)(bh + n);
        float4 d1 = *(const float4*)(bh + HH + n);
        float4 d2 = *(const float4*)(bh + 2 * HH + n);
        float4 ho = *(const float4*)(d_h0 + b * HH + n);
        float4 res;
        const float *pg0 = (const float*)&g0, *pg1 = (const float*)&g1, *pg2 = (const float*)&g2;
        const float *pw0 = (const float*)&w0, *pw1 = (const float*)&w1, *pw2 = (const float*)&w2;
        const float *pc0 = (const float*)&c0, *pc1 = (const float*)&c1, *pc2 = (const float*)&c2;
        const float *pd0 = (const float*)&d0, *pd1 = (const float*)&d1, *pd2 = (const float*)&d2;
        const float *pho = (const float*)&ho;
        float* pr = (float*)&res;
#pragma unroll
        for (int l = 0; l < 4; ++l) {
            float r  = sigmoidf_(pg0[l] + pd0[l] + xv * pw0[l] + pc0[l]);
            float z  = sigmoidf_(pg1[l] + pd1[l] + xv * pw1[l] + pc1[l]);
            float nn = tanhf(xv * pw2[l] + pc2[l] + r * (pg2[l] + pd2[l]));
            pr[l] = (1.f - z) * nn + z * pho[l];
        }
        *(float4*)(d_h0 + b * HH + n) = res;
        uint2 hv, lv;
        hv.x = pack_bf2(res.x, res.y);             hv.y = pack_bf2(res.z, res.w);
        lv.x = pack_bf2(bflo(res.x), bflo(res.y)); lv.y = pack_bf2(bflo(res.z), bflo(res.w));
        *(uint2*)(d_h0hi + b * HH + n) = hv;
        *(uint2*)(d_h0lo + b * HH + n) = lv;
    }
}

__device__ void actB(const float* __restrict__ bi1, const float* __restrict__ bh)
{
    int gtid = blockIdx.x * blockDim.x + threadIdx.x;
    int st   = gridDim.x * blockDim.x;
    for (int idx = gtid; idx < (BT * HH) / 4; idx += st) {
        int b = idx >> 7;
        int n = (idx & 127) << 2;
        const float* Pa = d_PB0[0] + b * NG + n;
        const float* Pb = d_PB0[1] + b * NG + n;
        const float* Qa = d_PB1[0] + b * NG + n;
        const float* Qb = d_PB1[1] + b * NG + n;
        float4 i0 = add4(*(const float4*)(Pa),          *(const float4*)(Pb));
        float4 i1 = add4(*(const float4*)(Pa + HH),     *(const float4*)(Pb + HH));
        float4 i2 = add4(*(const float4*)(Pa + 2 * HH), *(const float4*)(Pb + 2 * HH));
        float4 h0g = add4(*(const float4*)(Qa),          *(const float4*)(Qb));
        float4 h1g = add4(*(const float4*)(Qa + HH),     *(const float4*)(Qb + HH));
        float4 h2g = add4(*(const float4*)(Qa + 2 * HH), *(const float4*)(Qb + 2 * HH));
        float4 c0 = *(const float4*)(bi1 + n);
        float4 c1 = *(const float4*)(bi1 + HH + n);
        float4 c2 = *(const float4*)(bi1 + 2 * HH + n);
        float4 d0 = *(const float4*)(bh + NG + n);
        float4 d1 = *(const float4*)(bh + NG + HH + n);
        float4 d2 = *(const float4*)(bh + NG + 2 * HH + n);
        float4 ho = *(const float4*)(d_h1 + b * HH + n);
        float4 res;
        const float *pi0 = (const float*)&i0, *pi1 = (const float*)&i1, *pi2 = (const float*)&i2;
        const float *ph0 = (const float*)&h0g, *ph1 = (const float*)&h1g, *ph2 = (const float*)&h2g;
        const float *pc0 = (const float*)&c0, *pc1 = (const float*)&c1, *pc2 = (const float*)&c2;
        const float *pd0 = (const float*)&d0, *pd1 = (const float*)&d1, *pd2 = (const float*)&d2;
        const float *pho = (const float*)&ho;
        float* pr = (float*)&res;
#pragma unroll
        for (int l = 0; l < 4; ++l) {
            float r  = sigmoidf_(pi0[l] + pc0[l] + ph0[l] + pd0[l]);
            float z  = sigmoidf_(pi1[l] + pc1[l] + ph1[l] + pd1[l]);
            float nn = tanhf(pi2[l] + pc2[l] + r * (ph2[l] + pd2[l]));
            pr[l] = (1.f - z) * nn + z * pho[l];
        }
        *(float4*)(d_h1 + b * HH + n) = res;
        uint2 hv, lv;
        hv.x = pack_bf2(res.x, res.y);             hv.y = pack_bf2(res.z, res.w);
        lv.x = pack_bf2(bflo(res.x), bflo(res.y)); lv.y = pack_bf2(bflo(res.z), bflo(res.w));
        *(uint2*)(d_h1hi + b * HH + n) = hv;
        *(uint2*)(d_h1lo + b * HH + n) = lv;
    }
}

// ---------------- final FC ----------------
__device__ void fcOut(const float* __restrict__ fcw, const float* __restrict__ fcb,
                      float* __restrict__ out)
{
    __shared__ float red[2][8];
    if (blockIdx.x >= 128) return;
    for (int s = 0; s < 2; ++s) {
        int b = blockIdx.x * 2 + s;
        float p0 = 0.f, p1 = 0.f;
        for (int k = threadIdx.x; k < HH; k += NTHR) {
            float h = d_h1[b * HH + k];
            p0 += h * fcw[k];
            p1 += h * fcw[HH + k];
        }
#pragma unroll
        for (int o = 16; o; o >>= 1) {
            p0 += __shfl_down_sync(0xffffffffu, p0, o);
            p1 += __shfl_down_sync(0xffffffffu, p1, o);
        }
        int w = threadIdx.x >> 5;
        if ((threadIdx.x & 31) == 0) { red[0][w] = p0; red[1][w] = p1; }
        __syncthreads();
        if (threadIdx.x == 0) {
            float a0 = 0.f, a1 = 0.f;
#pragma unroll
            for (int ww = 0; ww < 8; ++ww) { a0 += red[0][ww]; a1 += red[1][ww]; }
            out[b * 2 + 0] = a0 + fcb[0];
            out[b * 2 + 1] = a1 + fcb[1];
        }
        __syncthreads();
    }
}

// ---------------- persistent kernel ----------------
__global__ void __launch_bounds__(NTHR, 2)
gru_persistent(const float* __restrict__ x,   const float* __restrict__ Wi0,
               const float* __restrict__ bi0, const float* __restrict__ Wi1,
               const float* __restrict__ bi1, const float* __restrict__ Wh,
               const float* __restrict__ bh,  const float* __restrict__ fcw,
               const float* __restrict__ fcb, float* __restrict__ out)
{
    extern __shared__ char smem[];
    const unsigned smem_u = s2u(smem);

    // tile assignment: u = ksel*144 + gsel*48 + tb
    const int u     = blockIdx.x;
    const int ksel  = u / 144;
    const int inner = u % 144;
    const int gsel  = inner / 48;      // 0: gi1, 1: gh1, 2: gh0(next step)
    const int tb    = inner % 48;
    const int m0    = (tb / 24) * 128;
    const int n0    = (tb % 24) * 64;
    const int kbase = ksel * KSL;

    const __nv_bfloat16* Agh = (gsel == 1) ? d_h1hi : d_h0hi;
    const __nv_bfloat16* Agl = (gsel == 1) ? d_h1lo : d_h0lo;
    float* Cg = (gsel == 0) ? d_PB0[ksel] : ((gsel == 1) ? d_PB1[ksel] : d_GA[ksel]);

    {
        const float* Wsl = (gsel == 0) ? (Wi1 + n0 * HH + kbase)
                         : (gsel == 1) ? (Wh + NG * HH + n0 * HH + kbase)
                                       : (Wh + n0 * HH + kbase);
        preloadW(Wsl, smem);
    }
    __syncthreads();

    actA(x, Wi0, bi0, bh, 0);          // h0(0); GA/h zeroed by init
    gridBarrier();

    for (int t = 0; t < TT - 1; ++t) {
        tileStep(Agh, Agl, Cg, m0, n0, kbase, smem, smem_u);
        gridBarrier();
        actB(bi1, bh);                 // h1(t)
        actA(x, Wi0, bi0, bh, t + 1);  // h0(t+1)
        gridBarrier();
    }

    if (gsel < 2) tileStep(Agh, Agl, Cg, m0, n0, kbase, smem, smem_u);  // last step
    gridBarrier();
    actB(bi1, bh);
    gridBarrier();

    fcOut(fcw, fcb, out);
}

// ---------------- launch ----------------
extern "C" void kernel_launch(void* const* d_in, const int* in_sizes, int n_in,
                              void* d_out, int out_size)
{
    (void)in_sizes; (void)n_in; (void)out_size;
    const float* x   = (const float*)d_in[0];
    const float* Wi0 = (const float*)d_in[1];
    const float* bi0 = (const float*)d_in[2];
    const float* Wi1 = (const float*)d_in[3];
    const float* bi1 = (const float*)d_in[4];
    const float* Wh  = (const float*)d_in[5];
    const float* bh  = (const float*)d_in[6];
    const float* fcw = (const float*)d_in[7];
    const float* fcb = (const float*)d_in[8];
    float* out = (float*)d_out;

    cudaFuncSetAttribute(gru_persistent,
                         cudaFuncAttributeMaxDynamicSharedMemorySize, SMEM_BYTES);

    gru_init<<<64, 256>>>();
    gru_persistent<<<NCTA, NTHR, SMEM_BYTES>>>(x, Wi0, bi0, Wi1, bi1, Wh, bh,
                                               fcw, fcb, out);
}

// round 17
// speedup vs baseline: 1.3259x; 1.0759x over previous
#include <cuda_runtime.h>
#include <cuda_bf16.h>
#include <math.h>

// GRU: B=256, T=512, H=512, L=2, O=2.
// Persistent kernel; bf16 hi/lo split GEMM on mma.sync.m16n8k16 (fp32 accum).
// Round-11 gemm (144 x 128x64 tiles, pinned W, 3-stage cp.async) + group-local
// act: after its tile, each CTA syncs with its 6-tile (or 3-tile) group on a
// monotonic counter and computes 1/6 (1/3) of that block's activation.
// ONE global barrier per step (race-free hierarchical, round-14 validated).
// h state ping-pongs by step parity.

#define BT 256
#define TT 512
#define HH 512
#define NG 1536
#define NCTA 148
#define NTHR 256

#define WST 520                        // W smem row stride (bf16 elems)
#define AST 40                         // A smem row stride (bf16 elems)
#define SMEM_W (64 * WST * 2)          // 66,560 B per W array (hi or lo)
#define ABUF   (128 * AST * 2)         // 10,240 B per (stage, hi/lo)
#define W_OFF  0
#define A_OFF  (2 * SMEM_W)            // 133,120
#define NSTAGE 3
#define NCHUNK 16                      // 16 chunks x 32 k
#define SMEM_BYTES (A_OFF + NSTAGE * 2 * ABUF)   // 194,560 B

// ---------------- persistent device state (h ping-pong by parity) ----------------
__device__ __align__(16) float d_h0f[2 * BT * HH];
__device__ __align__(16) float d_h1f[2 * BT * HH];
__device__ __align__(16) __nv_bfloat16 d_h0hi[2 * BT * HH];
__device__ __align__(16) __nv_bfloat16 d_h0lo[2 * BT * HH];
__device__ __align__(16) __nv_bfloat16 d_h1hi[2 * BT * HH];
__device__ __align__(16) __nv_bfloat16 d_h1lo[2 * BT * HH];
__device__ __align__(16) float d_GA[BT * NG];
__device__ __align__(16) float d_PB0[BT * NG];
__device__ __align__(16) float d_PB1[BT * NG];
// monotonic counters (zeroed each launch by gru_init)
__device__ unsigned d_grpCount[16 * 32];     // global barrier groups
__device__ unsigned d_rootCount;
__device__ volatile unsigned d_barGen;
__device__ unsigned d_ag1[16 * 32];          // layer-1 act groups (6 arrivals/step)
__device__ unsigned d_ag0[16 * 32];          // layer-0 act groups (3 arrivals/step)

__global__ void gru_init()
{
    int i  = blockIdx.x * blockDim.x + threadIdx.x;
    int st = gridDim.x * blockDim.x;
    for (int e = i; e < 2 * BT * HH; e += st) { d_h0f[e] = 0.f; d_h1f[e] = 0.f; }
    unsigned* z0 = (unsigned*)d_h0hi; unsigned* z1 = (unsigned*)d_h0lo;
    unsigned* z2 = (unsigned*)d_h1hi; unsigned* z3 = (unsigned*)d_h1lo;
    for (int e = i; e < BT * HH; e += st) { z0[e] = 0u; z1[e] = 0u; z2[e] = 0u; z3[e] = 0u; }
    for (int e = i; e < BT * NG; e += st) d_GA[e] = 0.f;
    if (i < 16 * 32) { d_grpCount[i] = 0u; d_ag1[i] = 0u; d_ag0[i] = 0u; }
    if (i == 0) { d_rootCount = 0u; d_barGen = 0u; }
}

// ---------------- race-free hierarchical global barrier (monotonic) ----------------
__device__ __forceinline__ void gridBarrier()
{
    __syncthreads();
    if (threadIdx.x == 0) {
        __threadfence();
        unsigned gen = d_barGen;
        unsigned grp = blockIdx.x & 15u;
        unsigned gsz = (grp < (NCTA & 15u)) ? (NCTA / 16 + 1) : (NCTA / 16);
        unsigned arrived = atomicAdd(&d_grpCount[grp * 32], 1u) + 1u;
        if (arrived == (gen + 1u) * gsz) {
            unsigned rootArr = atomicAdd(&d_rootCount, 1u) + 1u;
            if (rootArr == (gen + 1u) * 16u) {
                __threadfence();
                d_barGen = gen + 1u;
            }
        }
        while (d_barGen == gen) __nanosleep(32);
        __threadfence();
    }
    __syncthreads();
}

// ---------------- group-local sync (monotonic; release C writes / acquire peers') ----------------
__device__ __forceinline__ void groupSync(unsigned* cnt, unsigned need, int t)
{
    __syncthreads();                       // collect this CTA's C stores
    if (threadIdx.x == 0) {
        __threadfence();                   // release
        atomicAdd(cnt, 1u);
        unsigned target = need * (unsigned)(t + 1);
        while (*(volatile unsigned*)cnt < target) __nanosleep(32);
        __threadfence();                   // acquire
    }
    __syncthreads();
}

// ---------------- cp.async + misc PTX ----------------
__device__ __forceinline__ unsigned s2u(const void* p)
{
    unsigned a;
    asm("{ .reg .u64 t; cvta.to.shared.u64 t, %1; cvt.u32.u64 %0, t; }" : "=r"(a) : "l"(p));
    return a;
}
#define CPA16(d, s)  asm volatile("cp.async.cg.shared.global [%0], [%1], 16;" :: "r"(d), "l"(s) : "memory")
#define CP_COMMIT()  asm volatile("cp.async.commit_group;" ::: "memory")
#define CP_WAIT2()   asm volatile("cp.async.wait_group 2;" ::: "memory")
#define CP_WAIT0()   asm volatile("cp.async.wait_group 0;" ::: "memory")

#define MMA16816(C, A, b0, b1)                                                  \
    asm volatile("mma.sync.aligned.m16n8k16.row.col.f32.bf16.bf16.f32 "         \
                 "{%0,%1,%2,%3},{%4,%5,%6,%7},{%8,%9},{%0,%1,%2,%3};"           \
                 : "+f"((C)[0]), "+f"((C)[1]), "+f"((C)[2]), "+f"((C)[3])       \
                 : "r"((A)[0]), "r"((A)[1]), "r"((A)[2]), "r"((A)[3]),          \
                   "r"(b0), "r"(b1))

// ---------------- bf16 split helpers ----------------
__device__ __forceinline__ unsigned pack_bf2(float a, float b)
{
    __nv_bfloat162 t = __floats2bfloat162_rn(a, b);
    return *reinterpret_cast<unsigned*>(&t);
}
__device__ __forceinline__ float bflo(float v)
{
    return v - __bfloat162float(__float2bfloat16_rn(v));
}

// ---------------- one-time weight slice -> smem (bf16 hi/lo) ----------------
__device__ void preloadW(const float* __restrict__ Wsl, char* smem)
{
    __nv_bfloat16* Whi = (__nv_bfloat16*)(smem + W_OFF);
    __nv_bfloat16* Wlo = (__nv_bfloat16*)(smem + W_OFF + SMEM_W);
    for (int idx = threadIdx.x; idx < 64 * (HH / 4); idx += NTHR) {
        int n  = idx >> 7;
        int k4 = (idx & 127) << 2;
        float4 w = *(const float4*)(Wsl + n * HH + k4);
        uint2 hv, lv;
        hv.x = pack_bf2(w.x, w.y);             hv.y = pack_bf2(w.z, w.w);
        lv.x = pack_bf2(bflo(w.x), bflo(w.y)); lv.y = pack_bf2(bflo(w.z), bflo(w.w));
        *(uint2*)(Whi + n * WST + k4) = hv;
        *(uint2*)(Wlo + n * WST + k4) = lv;
    }
}

// ---------------- cp.async stage of one 32-k A chunk (hi+lo) ----------------
__device__ __forceinline__ void issueChunk(const __nv_bfloat16* __restrict__ Ahi,
                                           const __nv_bfloat16* __restrict__ Alo,
                                           unsigned smem_u, int stage, int m0, int c)
{
    int t = threadIdx.x;
    int row = t >> 1, half = t & 1;
    const char* gh = (const char*)(Ahi + (m0 + row) * HH + c * 32 + half * 16);
    const char* gl = (const char*)(Alo + (m0 + row) * HH + c * 32 + half * 16);
    unsigned bh = smem_u + A_OFF + (stage * 2 + 0) * ABUF + row * (AST * 2) + half * 32;
    unsigned bl = smem_u + A_OFF + (stage * 2 + 1) * ABUF + row * (AST * 2) + half * 32;
    CPA16(bh, gh);      CPA16(bh + 16, gh + 16);
    CPA16(bl, gl);      CPA16(bl + 16, gl + 16);
}

// ---------------- per-step 128x64xK512 tile gemm (round-11 proven) ----------------
__device__ void tileStep(const __nv_bfloat16* __restrict__ Agh,
                         const __nv_bfloat16* __restrict__ Agl,
                         float* __restrict__ Cg, int m0, int n0,
                         char* smem, unsigned smem_u)
{
    const __nv_bfloat16* Whi = (const __nv_bfloat16*)(smem + W_OFF);
    const __nv_bfloat16* Wlo = (const __nv_bfloat16*)(smem + W_OFF + SMEM_W);

    const int tid  = threadIdx.x;
    const int wid  = tid >> 5;
    const int lane = tid & 31;
    const int g    = lane >> 2;
    const int t4   = lane & 3;
    const int wm   = wid & 1;
    const int wn   = wid >> 1;

    int aoff[4];
#pragma unroll
    for (int ma = 0; ma < 4; ++ma)
        aoff[ma] = (wm * 64 + ma * 16 + g) * AST + 2 * t4;
    int boff[2];
#pragma unroll
    for (int na = 0; na < 2; ++na)
        boff[na] = (wn * 16 + na * 8 + g) * WST + 2 * t4;

    float acc[4][2][4];
#pragma unroll
    for (int ma = 0; ma < 4; ++ma)
#pragma unroll
        for (int na = 0; na < 2; ++na)
#pragma unroll
            for (int q = 0; q < 4; ++q) acc[ma][na][q] = 0.f;

#pragma unroll
    for (int s = 0; s < NSTAGE; ++s) {
        issueChunk(Agh, Agl, smem_u, s, m0, s);
        CP_COMMIT();
    }

#pragma unroll 1
    for (int c = 0; c < NCHUNK; ++c) {
        int stg = c % NSTAGE;
        CP_WAIT2();
        __syncthreads();

        const __nv_bfloat16* Ah = (const __nv_bfloat16*)(smem + A_OFF + (stg * 2 + 0) * ABUF);
        const __nv_bfloat16* Al = (const __nv_bfloat16*)(smem + A_OFF + (stg * 2 + 1) * ABUF);
#pragma unroll
        for (int ks = 0; ks < 32; ks += 16) {
            unsigned ah[4][4], al[4][4];
#pragma unroll
            for (int ma = 0; ma < 4; ++ma) {
                int o = aoff[ma] + ks;
                ah[ma][0] = *(const unsigned*)(Ah + o);
                ah[ma][1] = *(const unsigned*)(Ah + o + 8 * AST);
                ah[ma][2] = *(const unsigned*)(Ah + o + 8);
                ah[ma][3] = *(const unsigned*)(Ah + o + 8 * AST + 8);
                al[ma][0] = *(const unsigned*)(Al + o);
                al[ma][1] = *(const unsigned*)(Al + o + 8 * AST);
                al[ma][2] = *(const unsigned*)(Al + o + 8);
                al[ma][3] = *(const unsigned*)(Al + o + 8 * AST + 8);
            }
#pragma unroll
            for (int na = 0; na < 2; ++na) {
                int ob = boff[na] + c * 32 + ks;
                unsigned bh0 = *(const unsigned*)(Whi + ob);
                unsigned bh1 = *(const unsigned*)(Whi + ob + 8);
                unsigned bl0 = *(const unsigned*)(Wlo + ob);
                unsigned bl1 = *(const unsigned*)(Wlo + ob + 8);
#pragma unroll
                for (int ma = 0; ma < 4; ++ma) {
                    MMA16816(acc[ma][na], ah[ma], bh0, bh1);
                    MMA16816(acc[ma][na], ah[ma], bl0, bl1);
                    MMA16816(acc[ma][na], al[ma], bh0, bh1);
                }
            }
        }

        __syncthreads();
        if (c + NSTAGE < NCHUNK)
            issueChunk(Agh, Agl, smem_u, stg, m0, c + NSTAGE);
        CP_COMMIT();
    }
    CP_WAIT0();

#pragma unroll
    for (int ma = 0; ma < 4; ++ma) {
        int row = m0 + wm * 64 + ma * 16 + g;
#pragma unroll
        for (int na = 0; na < 2; ++na) {
            int col = n0 + wn * 16 + na * 8 + 2 * t4;
            float2 v0; v0.x = acc[ma][na][0]; v0.y = acc[ma][na][1];
            float2 v1; v1.x = acc[ma][na][2]; v1.y = acc[ma][na][3];
            *(float2*)(Cg + row * NG + col)       = v0;
            *(float2*)(Cg + (row + 8) * NG + col) = v1;
        }
    }
}

// ---------------- act slices (exact; emit fp32 + bf16 hi/lo to parity^1) ----------------
__device__ __forceinline__ float sigmoidf_(float v) { return 1.f / (1.f + expf(-v)); }

// h1 slice of block [m0, n0w): it-range [lo, hi) over 2048 units (row*16 + c4)
__device__ void actH1slice(int m0, int n0w, int lo, int hi, int par,
                           const float* __restrict__ bi1, const float* __restrict__ bh)
{
    const int po = par * BT * HH, pn = (par ^ 1) * BT * HH;
    for (int it = lo + threadIdx.x; it < hi; it += NTHR) {
        int row = it >> 4, c4 = it & 15;
        int b = m0 + row;
        int n = n0w + (c4 << 2);
        const float* P0 = d_PB0 + b * NG + n;
        const float* P1 = d_PB1 + b * NG + n;
        float4 i0 = __ldcg((const float4*)(P0));
        float4 i1 = __ldcg((const float4*)(P0 + 512));
        float4 i2 = __ldcg((const float4*)(P0 + 1024));
        float4 g0 = __ldcg((const float4*)(P1));
        float4 g1 = __ldcg((const float4*)(P1 + 512));
        float4 g2 = __ldcg((const float4*)(P1 + 1024));
        float4 c0 = *(const float4*)(bi1 + n);
        float4 c1 = *(const float4*)(bi1 + 512 + n);
        float4 c2 = *(const float4*)(bi1 + 1024 + n);
        float4 d0 = *(const float4*)(bh + NG + n);
        float4 d1 = *(const float4*)(bh + NG + 512 + n);
        float4 d2 = *(const float4*)(bh + NG + 1024 + n);
        float4 ho = *(const float4*)(d_h1f + po + b * HH + n);
        float4 res;
        const float *pi0 = (const float*)&i0, *pi1 = (const float*)&i1, *pi2 = (const float*)&i2;
        const float *pg0 = (const float*)&g0, *pg1 = (const float*)&g1, *pg2 = (const float*)&g2;
        const float *pc0 = (const float*)&c0, *pc1 = (const float*)&c1, *pc2 = (const float*)&c2;
        const float *pd0 = (const float*)&d0, *pd1 = (const float*)&d1, *pd2 = (const float*)&d2;
        const float *pho = (const float*)&ho;
        float* pr = (float*)&res;
#pragma unroll
        for (int l = 0; l < 4; ++l) {
            float r  = sigmoidf_(pi0[l] + pc0[l] + pg0[l] + pd0[l]);
            float z  = sigmoidf_(pi1[l] + pc1[l] + pg1[l] + pd1[l]);
            float nn = tanhf(pi2[l] + pc2[l] + r * (pg2[l] + pd2[l]));
            pr[l] = (1.f - z) * nn + z * pho[l];
        }
        *(float4*)(d_h1f + pn + b * HH + n) = res;
        uint2 hv, lv;
        hv.x = pack_bf2(res.x, res.y);             hv.y = pack_bf2(res.z, res.w);
        lv.x = pack_bf2(bflo(res.x), bflo(res.y)); lv.y = pack_bf2(bflo(res.z), bflo(res.w));
        *(uint2*)(d_h1hi + pn + b * HH + n) = hv;
        *(uint2*)(d_h1lo + pn + b * HH + n) = lv;
    }
}

// h0(t+1) slice from GA + x[:, t+1]
__device__ void actH0slice(int m0, int n0w, int lo, int hi, int par, int t,
                           const float* __restrict__ x, const float* __restrict__ Wi0,
                           const float* __restrict__ bi0, const float* __restrict__ bh)
{
    const int po = par * BT * HH, pn = (par ^ 1) * BT * HH;
    for (int it = lo + threadIdx.x; it < hi; it += NTHR) {
        int row = it >> 4, c4 = it & 15;
        int b = m0 + row;
        int n = n0w + (c4 << 2);
        float xv = x[b * TT + t + 1];
        const float* G = d_GA + b * NG + n;
        float4 g0 = __ldcg((const float4*)(G));
        float4 g1 = __ldcg((const float4*)(G + 512));
        float4 g2 = __ldcg((const float4*)(G + 1024));
        float4 w0 = *(const float4*)(Wi0 + n);
        float4 w1 = *(const float4*)(Wi0 + 512 + n);
        float4 w2 = *(const float4*)(Wi0 + 1024 + n);
        float4 c0 = *(const float4*)(bi0 + n);
        float4 c1 = *(const float4*)(bi0 + 512 + n);
        float4 c2 = *(const float4*)(bi0 + 1024 + n);
        float4 d0 = *(const float4*)(bh + n);
        float4 d1 = *(const float4*)(bh + 512 + n);
        float4 d2 = *(const float4*)(bh + 1024 + n);
        float4 ho = *(const float4*)(d_h0f + po + b * HH + n);
        float4 res;
        const float *pg0 = (const float*)&g0, *pg1 = (const float*)&g1, *pg2 = (const float*)&g2;
        const float *pw0 = (const float*)&w0, *pw1 = (const float*)&w1, *pw2 = (const float*)&w2;
        const float *pc0 = (const float*)&c0, *pc1 = (const float*)&c1, *pc2 = (const float*)&c2;
        const float *pd0 = (const float*)&d0, *pd1 = (const float*)&d1, *pd2 = (const float*)&d2;
        const float *pho = (const float*)&ho;
        float* pr = (float*)&res;
#pragma unroll
        for (int l = 0; l < 4; ++l) {
            float r  = sigmoidf_(pg0[l] + pd0[l] + xv * pw0[l] + pc0[l]);
            float z  = sigmoidf_(pg1[l] + pd1[l] + xv * pw1[l] + pc1[l]);
            float nn = tanhf(xv * pw2[l] + pc2[l] + r * (pg2[l] + pd2[l]));
            pr[l] = (1.f - z) * nn + z * pho[l];
        }
        *(float4*)(d_h0f + pn + b * HH + n) = res;
        uint2 hv, lv;
        hv.x = pack_bf2(res.x, res.y);             hv.y = pack_bf2(res.z, res.w);
        lv.x = pack_bf2(bflo(res.x), bflo(res.y)); lv.y = pack_bf2(bflo(res.z), bflo(res.w));
        *(uint2*)(d_h0hi + pn + b * HH + n) = hv;
        *(uint2*)(d_h0lo + pn + b * HH + n) = lv;
    }
}

// ---------------- final FC (h1(511) at t=511, par=1 -> buffer 0) ----------------
__device__ void fcOut(const float* __restrict__ fcw, const float* __restrict__ fcb,
                      float* __restrict__ out)
{
    __shared__ float red[2][8];
    if (blockIdx.x >= 128) return;
    for (int s = 0; s < 2; ++s) {
        int b = blockIdx.x * 2 + s;
        float p0 = 0.f, p1 = 0.f;
        for (int k = threadIdx.x; k < HH; k += NTHR) {
            float h = d_h1f[b * HH + k];
            p0 += h * fcw[k];
            p1 += h * fcw[HH + k];
        }
#pragma unroll
        for (int o = 16; o; o >>= 1) {
            p0 += __shfl_down_sync(0xffffffffu, p0, o);
            p1 += __shfl_down_sync(0xffffffffu, p1, o);
        }
        int w = threadIdx.x >> 5;
        if ((threadIdx.x & 31) == 0) { red[0][w] = p0; red[1][w] = p1; }
        __syncthreads();
        if (threadIdx.x == 0) {
            float a0 = 0.f, a1 = 0.f;
#pragma unroll
            for (int ww = 0; ww < 8; ++ww) { a0 += red[0][ww]; a1 += red[1][ww]; }
            out[b * 2 + 0] = a0 + fcb[0];
            out[b * 2 + 1] = a1 + fcb[1];
        }
        __syncthreads();
    }
}

// ---------------- persistent kernel ----------------
__global__ void __launch_bounds__(NTHR, 1)
gru_persistent(const float* __restrict__ x,   const float* __restrict__ Wi0,
               const float* __restrict__ bi0, const float* __restrict__ Wi1,
               const float* __restrict__ bi1, const float* __restrict__ Wh,
               const float* __restrict__ bh,  const float* __restrict__ fcw,
               const float* __restrict__ fcb, float* __restrict__ out)
{
    extern __shared__ char smem[];
    const unsigned smem_u = s2u(smem);
    const int tid = threadIdx.x;

    // tile assignment: u = gsel*48 + m*24 + gate*8 + nw
    const int u = blockIdx.x;
    const bool active = (u < 144);
    const int gsel = u / 48;           // 0: gi1, 1: gh1, 2: gh0(next step)
    const int tb   = u % 48;
    const int m    = tb / 24;
    const int tc   = tb % 24;
    const int gate = tc / 8;
    const int nw   = tc % 8;
    const int m0   = m * 128;
    const int n0   = tc * 64;          // gate*512 + nw*64
    const int n0w  = nw * 64;
    const int gid  = m * 8 + nw;       // act-group id 0..15
    const int rank = (gsel < 2) ? (gsel * 3 + gate) : gate;
    // act slice [lo, hi) over 2048 units
    const int nparts = (gsel < 2) ? 6 : 3;
    const int lo = (2048 * rank) / nparts;
    const int hi = (2048 * (rank + 1)) / nparts;

    float* Cg = (gsel == 0) ? d_PB0 : ((gsel == 1) ? d_PB1 : d_GA);

    if (active) {
        const float* Wsl = (gsel == 0) ? (Wi1 + n0 * HH)
                         : (gsel == 1) ? (Wh + NG * HH + n0 * HH)
                                       : (Wh + n0 * HH);
        preloadW(Wsl, smem);
    }
    __syncthreads();

    // prologue: h0(0) -> parity buffer 0 (h_old = 0, GA = 0)
    {
        int gtid = blockIdx.x * NTHR + tid;
        int st   = gridDim.x * NTHR;
        for (int idx = gtid; idx < (BT * HH) / 4; idx += st) {
            int b = idx >> 7;
            int n = (idx & 127) << 2;
            float xv = x[b * TT];
            float4 w0 = *(const float4*)(Wi0 + n);
            float4 w1 = *(const float4*)(Wi0 + 512 + n);
            float4 w2 = *(const float4*)(Wi0 + 1024 + n);
            float4 c0 = *(const float4*)(bi0 + n);
            float4 c1 = *(const float4*)(bi0 + 512 + n);
            float4 c2 = *(const float4*)(bi0 + 1024 + n);
            float4 d0 = *(const float4*)(bh + n);
            float4 d1 = *(const float4*)(bh + 512 + n);
            float4 d2 = *(const float4*)(bh + 1024 + n);
            float4 res;
            const float *pw0 = (const float*)&w0, *pw1 = (const float*)&w1, *pw2 = (const float*)&w2;
            const float *pc0 = (const float*)&c0, *pc1 = (const float*)&c1, *pc2 = (const float*)&c2;
            const float *pd0 = (const float*)&d0, *pd1 = (const float*)&d1, *pd2 = (const float*)&d2;
            float* pr = (float*)&res;
#pragma unroll
            for (int l = 0; l < 4; ++l) {
                float r  = sigmoidf_(xv * pw0[l] + pc0[l] + pd0[l]);
                float z  = sigmoidf_(xv * pw1[l] + pc1[l] + pd1[l]);
                float nn = tanhf(xv * pw2[l] + pc2[l] + r * pd2[l]);
                pr[l] = (1.f - z) * nn;
            }
            *(float4*)(d_h0f + b * HH + n) = res;
            uint2 hv, lv;
            hv.x = pack_bf2(res.x, res.y);             hv.y = pack_bf2(res.z, res.w);
            lv.x = pack_bf2(bflo(res.x), bflo(res.y)); lv.y = pack_bf2(bflo(res.z), bflo(res.w));
            *(uint2*)(d_h0hi + b * HH + n) = hv;
            *(uint2*)(d_h0lo + b * HH + n) = lv;
        }
    }
    gridBarrier();

    for (int t = 0; t < TT; ++t) {
        int par = t & 1;
        bool run = active && (gsel < 2 || t < TT - 1);   // gh0 skips last step
        if (run) {
            const __nv_bfloat16* Agh = ((gsel == 1) ? d_h1hi : d_h0hi) + par * BT * HH;
            const __nv_bfloat16* Agl = ((gsel == 1) ? d_h1lo : d_h0lo) + par * BT * HH;
            tileStep(Agh, Agl, Cg, m0, n0, smem, smem_u);
            // group-local sync, then this CTA's act slice
            if (gsel < 2) {
                groupSync(&d_ag1[gid * 32], 6u, t);
                actH1slice(m0, n0w, lo, hi, par, bi1, bh);
            } else {
                groupSync(&d_ag0[gid * 32], 3u, t);
                actH0slice(m0, n0w, lo, hi, par, t, x, Wi0, bi0, bh);
            }
        }
        gridBarrier();
    }

    fcOut(fcw, fcb, out);
}

// ---------------- launch ----------------
extern "C" void kernel_launch(void* const* d_in, const int* in_sizes, int n_in,
                              void* d_out, int out_size)
{
    (void)in_sizes; (void)n_in; (void)out_size;
    const float* x   = (const float*)d_in[0];
    const float* Wi0 = (const float*)d_in[1];
    const float* bi0 = (const float*)d_in[2];
    const float* Wi1 = (const float*)d_in[3];
    const float* bi1 = (const float*)d_in[4];
    const float* Wh  = (const float*)d_in[5];
    const float* bh  = (const float*)d_in[6];
    const float* fcw = (const float*)d_in[7];
    const float* fcb = (const float*)d_in[8];
    float* out = (float*)d_out;

    cudaFuncSetAttribute(gru_persistent,
                         cudaFuncAttributeMaxDynamicSharedMemorySize, SMEM_BYTES);

    gru_init<<<64, 256>>>();
    gru_persistent<<<NCTA, NTHR, SMEM_BYTES>>>(x, Wi0, bi0, Wi1, bi1, Wh, bh,
                                               fcw, fcb, out);
}